// round 9
// baseline (speedup 1.0000x reference)
#include <cuda_runtime.h>
#include <cuda_fp16.h>

// Guided filter, RADIUS=8, EPS=0.01, (8,3,1024,1024) fp32.
// Vertical-FIRST separable box: per-thread vertical running sums of raw
// series (pointwise lead/trail update, own cols only), then ONE horizontal
// box per output row via chain-free prefix identity with smem warp-edge halos.
// kA: x,y -> (a,b) packed half2.  kB: (a,b),x -> out.

#define W     1024
#define Hh    1024
#define IMGS  24
#define HW    (Hh * W)
#define TOTAL (IMGS * HW)
#define RAD   8
#define EPSF  0.01f
#define SEGR  32
#define SEGS  (Hh / SEGR)
#define TPB   128
#define NW    4
#define FULLM 0xffffffffu

__device__ __align__(16) __half2 g_ab[TOTAL];

__device__ __forceinline__ unsigned int pack_h2(float a, float b) {
    __half2 h = __floats2half2_rn(a, b);
    return *reinterpret_cast<unsigned int*>(&h);
}
__device__ __forceinline__ void dec_h2(unsigned int u, float& a, float& b) {
    __half2 h = *reinterpret_cast<__half2*>(&u);
    float2 f = __half22float2(h);
    a = f.x; b = f.y;
}

// 17-wide horizontal box of per-lane vertical sums V[8].
// box[col0+j] = suffix_{left}(j) + U + prefix_{right}(j+1); neighbors via
// shfl, warp-edges via smem halos (hsuf valid on lane 0, hpre on lane 31).
__device__ __forceinline__ void boxV(const float V[8], const float hsuf[8],
                                     const float hpre[8], int lane, float bx[8]) {
    float p[9]; p[0] = 0.f;
    #pragma unroll
    for (int j = 0; j < 8; j++) p[j + 1] = p[j] + V[j];
    float U = p[8];
    float sufL[8], preR[8];
    #pragma unroll
    for (int j = 0; j < 8; j++) {
        float t = __shfl_up_sync(FULLM, U - p[j], 1);
        sufL[j] = (lane == 0) ? hsuf[j] : t;
    }
    #pragma unroll
    for (int j = 0; j < 8; j++) {
        float t = __shfl_down_sync(FULLM, p[j + 1], 1);
        preR[j] = (lane == 31) ? hpre[j] : t;
    }
    #pragma unroll
    for (int j = 0; j < 8; j++) bx[j] = (sufL[j] + U) + preR[j];
}

// lane 0 publishes prefix sums of V, lane 31 suffix sums (for neighbor warps).
__device__ __forceinline__ void write_edges(const float V[8], float* pre_dst,
                                            float* suf_dst, int lane) {
    if (lane == 0) {
        float t[8]; float acc = 0.f;
        #pragma unroll
        for (int j = 0; j < 8; j++) { acc += V[j]; t[j] = acc; }
        *(float4*)(pre_dst)     = make_float4(t[0], t[1], t[2], t[3]);
        *(float4*)(pre_dst + 4) = make_float4(t[4], t[5], t[6], t[7]);
    } else if (lane == 31) {
        float t[8]; float acc = 0.f;
        #pragma unroll
        for (int j = 7; j >= 0; j--) { acc += V[j]; t[j] = acc; }
        *(float4*)(suf_dst)     = make_float4(t[0], t[1], t[2], t[3]);
        *(float4*)(suf_dst + 4) = make_float4(t[4], t[5], t[6], t[7]);
    }
}

// read halos: lane 0 takes left-neighbor-warp suffixes, lane 31 right prefixes.
__device__ __forceinline__ void get_halo(const float* sufsrc, const float* presrc,
                                         int warp, int lane,
                                         float hsuf[8], float hpre[8]) {
    #pragma unroll
    for (int j = 0; j < 8; j++) { hsuf[j] = 0.f; hpre[j] = 0.f; }
    if (lane == 0) {
        if (warp > 0) {
            float4 a = *(const float4*)sufsrc, b = *(const float4*)(sufsrc + 4);
            hsuf[0]=a.x; hsuf[1]=a.y; hsuf[2]=a.z; hsuf[3]=a.w;
            hsuf[4]=b.x; hsuf[5]=b.y; hsuf[6]=b.z; hsuf[7]=b.w;
        }
    } else if (lane == 31) {
        if (warp < NW - 1) {
            float4 a = *(const float4*)presrc, b = *(const float4*)(presrc + 4);
            hpre[0]=a.x; hpre[1]=a.y; hpre[2]=a.z; hpre[3]=a.w;
            hpre[4]=b.x; hpre[5]=b.y; hpre[6]=b.z; hpre[7]=b.w;
        }
    }
}

template<int SGN>
__device__ __forceinline__ void addA(const float* __restrict__ xr,
                                     const float* __restrict__ yr, int col0,
                                     float V0[8], float V1[8],
                                     float V2[8], float V3[8]) {
    float4 a0 = *(const float4*)(xr + col0), a1 = *(const float4*)(xr + col0 + 4);
    float4 b0 = *(const float4*)(yr + col0), b1 = *(const float4*)(yr + col0 + 4);
    float xv[8] = {a0.x,a0.y,a0.z,a0.w,a1.x,a1.y,a1.z,a1.w};
    float yv[8] = {b0.x,b0.y,b0.z,b0.w,b1.x,b1.y,b1.z,b1.w};
    #pragma unroll
    for (int j = 0; j < 8; j++) {
        if (SGN > 0) {
            V0[j] += xv[j];
            V1[j] += yv[j];
            V2[j] = fmaf(xv[j], xv[j], V2[j]);
            V3[j] = fmaf(xv[j], yv[j], V3[j]);
        } else {
            V0[j] -= xv[j];
            V1[j] -= yv[j];
            V2[j] = fmaf(-xv[j], xv[j], V2[j]);
            V3[j] = fmaf(-xv[j], yv[j], V3[j]);
        }
    }
}

template<int SGN>
__device__ __forceinline__ void addB(const __half2* __restrict__ abr, int col0,
                                     float Va[8], float Vb[8]) {
    uint4 p0 = *(const uint4*)(abr + col0);
    uint4 p1 = *(const uint4*)(abr + col0 + 4);
    unsigned int u[8] = {p0.x,p0.y,p0.z,p0.w,p1.x,p1.y,p1.z,p1.w};
    #pragma unroll
    for (int j = 0; j < 8; j++) {
        float a, b; dec_h2(u[j], a, b);
        if (SGN > 0) { Va[j] += a; Vb[j] += b; }
        else         { Va[j] -= a; Vb[j] -= b; }
    }
}

// ---------------------------------------------------------------------------
__global__ void __launch_bounds__(TPB) kA(const float* __restrict__ x,
                                          const float* __restrict__ y) {
    __shared__ __align__(16) float sm[2][NW][2][4][8]; // [par][warp][0=pre/1=suf][series][8]
    int img  = blockIdx.y;
    int s    = blockIdx.x * SEGR;
    int warp = threadIdx.x >> 5;
    int lane = threadIdx.x & 31;
    int col0 = (warp << 8) + lane * 8;
    const float* xb = x + img * HW;
    const float* yb = y + img * HW;

    float V0[8], V1[8], V2[8], V3[8];
    #pragma unroll
    for (int j = 0; j < 8; j++) { V0[j]=0.f; V1[j]=0.f; V2[j]=0.f; V3[j]=0.f; }

    for (int r = max(0, s - RAD); r <= s + RAD; r++)
        addA<+1>(xb + r * W, yb + r * W, col0, V0, V1, V2, V3);

    float inv_nx[8];
    #pragma unroll
    for (int j = 0; j < 8; j++) {
        int c = col0 + j;
        inv_nx[j] = __frcp_rn((float)(min(W - 1, c + RAD) - max(0, c - RAD) + 1));
    }

    __half2* gab = g_ab + img * HW;

    for (int o = s; o < s + SEGR; o++) {
        int par = o & 1;
        write_edges(V0, &sm[par][warp][0][0][0], &sm[par][warp][1][0][0], lane);
        write_edges(V1, &sm[par][warp][0][1][0], &sm[par][warp][1][1][0], lane);
        write_edges(V2, &sm[par][warp][0][2][0], &sm[par][warp][1][2][0], lane);
        write_edges(V3, &sm[par][warp][0][3][0], &sm[par][warp][1][3][0], lane);
        __syncthreads();

        float bx0[8], bx1[8], bx2[8], bx3[8], hsuf[8], hpre[8];
        int wl = (warp > 0) ? warp - 1 : 0;
        int wr = (warp < NW - 1) ? warp + 1 : NW - 1;
        get_halo(&sm[par][wl][1][0][0], &sm[par][wr][0][0][0], warp, lane, hsuf, hpre);
        boxV(V0, hsuf, hpre, lane, bx0);
        get_halo(&sm[par][wl][1][1][0], &sm[par][wr][0][1][0], warp, lane, hsuf, hpre);
        boxV(V1, hsuf, hpre, lane, bx1);
        get_halo(&sm[par][wl][1][2][0], &sm[par][wr][0][2][0], warp, lane, hsuf, hpre);
        boxV(V2, hsuf, hpre, lane, bx2);
        get_halo(&sm[par][wl][1][3][0], &sm[par][wr][0][3][0], warp, lane, hsuf, hpre);
        boxV(V3, hsuf, hpre, lane, bx3);

        float inv_ny = __frcp_rn((float)(min(Hh - 1, o + RAD) - max(0, o - RAD) + 1));
        unsigned int pk[8];
        #pragma unroll
        for (int j = 0; j < 8; j++) {
            float invN = inv_nx[j] * inv_ny;
            float mx = bx0[j] * invN, my = bx1[j] * invN;
            float varx = fmaf(-mx, mx, bx2[j] * invN);
            float cov  = fmaf(-mx, my, bx3[j] * invN);
            float a = __fdividef(cov, varx + EPSF);
            float b = fmaf(-a, mx, my);
            pk[j] = pack_h2(a, b);
        }
        uint4 u0, u1;
        u0.x = pk[0]; u0.y = pk[1]; u0.z = pk[2]; u0.w = pk[3];
        u1.x = pk[4]; u1.y = pk[5]; u1.z = pk[6]; u1.w = pk[7];
        *(uint4*)(gab + o * W + col0)     = u0;
        *(uint4*)(gab + o * W + col0 + 4) = u1;

        int lead = o + RAD + 1, trail = o - RAD;
        if (lead < Hh)
            addA<+1>(xb + lead * W, yb + lead * W, col0, V0, V1, V2, V3);
        if (trail >= 0)
            addA<-1>(xb + trail * W, yb + trail * W, col0, V0, V1, V2, V3);
    }
}

// ---------------------------------------------------------------------------
__global__ void __launch_bounds__(TPB) kB(const float* __restrict__ x,
                                          float* __restrict__ out) {
    __shared__ __align__(16) float sm[2][NW][2][2][8];
    int img  = blockIdx.y;
    int s    = blockIdx.x * SEGR;
    int warp = threadIdx.x >> 5;
    int lane = threadIdx.x & 31;
    int col0 = (warp << 8) + lane * 8;
    const __half2* abr = g_ab + img * HW;
    const float* xb = x + img * HW;
    float* ob = out + img * HW;

    float Va[8], Vb[8];
    #pragma unroll
    for (int j = 0; j < 8; j++) { Va[j]=0.f; Vb[j]=0.f; }

    for (int r = max(0, s - RAD); r <= s + RAD; r++)
        addB<+1>(abr + r * W, col0, Va, Vb);

    float inv_nx[8];
    #pragma unroll
    for (int j = 0; j < 8; j++) {
        int c = col0 + j;
        inv_nx[j] = __frcp_rn((float)(min(W - 1, c + RAD) - max(0, c - RAD) + 1));
    }

    for (int o = s; o < s + SEGR; o++) {
        int par = o & 1;
        write_edges(Va, &sm[par][warp][0][0][0], &sm[par][warp][1][0][0], lane);
        write_edges(Vb, &sm[par][warp][0][1][0], &sm[par][warp][1][1][0], lane);
        __syncthreads();

        float bxa[8], bxb[8], hsuf[8], hpre[8];
        int wl = (warp > 0) ? warp - 1 : 0;
        int wr = (warp < NW - 1) ? warp + 1 : NW - 1;
        get_halo(&sm[par][wl][1][0][0], &sm[par][wr][0][0][0], warp, lane, hsuf, hpre);
        boxV(Va, hsuf, hpre, lane, bxa);
        get_halo(&sm[par][wl][1][1][0], &sm[par][wr][0][1][0], warp, lane, hsuf, hpre);
        boxV(Vb, hsuf, hpre, lane, bxb);

        float inv_ny = __frcp_rn((float)(min(Hh - 1, o + RAD) - max(0, o - RAD) + 1));
        float4 x0 = *(const float4*)(xb + o * W + col0);
        float4 x1 = *(const float4*)(xb + o * W + col0 + 4);
        float xs[8] = {x0.x,x0.y,x0.z,x0.w,x1.x,x1.y,x1.z,x1.w};
        float os[8];
        #pragma unroll
        for (int j = 0; j < 8; j++) {
            float invN = inv_nx[j] * inv_ny;
            os[j] = fmaf(bxa[j] * invN, xs[j], bxb[j] * invN);
        }
        float4 o0, o1;
        o0.x = os[0]; o0.y = os[1]; o0.z = os[2]; o0.w = os[3];
        o1.x = os[4]; o1.y = os[5]; o1.z = os[6]; o1.w = os[7];
        *(float4*)(ob + o * W + col0)     = o0;
        *(float4*)(ob + o * W + col0 + 4) = o1;

        int lead = o + RAD + 1, trail = o - RAD;
        if (lead < Hh)
            addB<+1>(abr + lead * W, col0, Va, Vb);
        if (trail >= 0)
            addB<-1>(abr + trail * W, col0, Va, Vb);
    }
}

extern "C" void kernel_launch(void* const* d_in, const int* in_sizes, int n_in,
                              void* d_out, int out_size) {
    const float* x = (const float*)d_in[0];
    const float* y = (const float*)d_in[1];
    float* out = (float*)d_out;

    dim3 grid(SEGS, IMGS);
    kA<<<grid, TPB>>>(x, y);
    kB<<<grid, TPB>>>(x, out);
}